// round 5
// baseline (speedup 1.0000x reference)
#include <cuda_runtime.h>
#include <math.h>
#include <float.h>

#define NB 8
#define NT 2048
#define ND 1024
#define NP 512
#define NS 256

// ---------------- scratch (static __device__ — no allocations) ----------------
__device__ float g_scores[NB*NT];
__device__ float g_sscore[NB*NT];
__device__ int   g_summap[NB*NP];
__device__ int   g_src[NB*NP];
__device__ int   g_counts[NB];
__device__ float g_summ[NB*NP*NS];
__device__ float g_poolf[NB*NP*NS];
__device__ float g_q[NB*NT*NS];
__device__ float g_k[NB*NP*NS];
__device__ float g_v[NB*NP*ND];

// =============================================================================
// Kernel 1: scores = sigmoid(relu(X @ w1) @ w2).  One block = 32 tokens.
// fp32 FMA within 32-wide k-blocks, fp64 accumulation across blocks; h rounded
// to fp32 before relu; stage 2 + reduce + sigmoid in fp64 (rank-exactness).
// =============================================================================
__global__ __launch_bounds__(256) void score_kernel(
    const float* __restrict__ tokens, const float* __restrict__ w1,
    const float* __restrict__ w2)
{
    __shared__ float xs[32][33];
    __shared__ float ws[32][257];
    __shared__ float w2s[256];
    int tid = threadIdx.x;
    int tx = tid & 63, ty = tid >> 6;
    int r0 = blockIdx.x * 32;
    w2s[tid] = w2[tid];

    double accd[8][4];
#pragma unroll
    for (int r = 0; r < 8; r++)
#pragma unroll
        for (int c = 0; c < 4; c++) accd[r][c] = 0.0;

    for (int k0 = 0; k0 < ND; k0 += 32) {
#pragma unroll
        for (int l = 0; l < 4; l++) {
            int idx = tid + l*256; int t = idx >> 5, kk = idx & 31;
            xs[t][kk] = tokens[(size_t)(r0 + t)*ND + k0 + kk];
        }
#pragma unroll
        for (int l = 0; l < 32; l++) {
            int idx = tid + l*256; int kk = idx >> 8, j = idx & 255;
            ws[kk][j] = w1[(size_t)(k0 + kk)*NS + j];
        }
        __syncthreads();
        float blk[8][4];
#pragma unroll
        for (int r = 0; r < 8; r++)
#pragma unroll
            for (int c = 0; c < 4; c++) blk[r][c] = 0.f;
#pragma unroll
        for (int kk = 0; kk < 32; kk++) {
            float bw[4], ax[8];
#pragma unroll
            for (int c = 0; c < 4; c++) bw[c] = ws[kk][tx + 64*c];
#pragma unroll
            for (int r = 0; r < 8; r++) ax[r] = xs[ty*8 + r][kk];
#pragma unroll
            for (int r = 0; r < 8; r++)
#pragma unroll
                for (int c = 0; c < 4; c++) blk[r][c] += ax[r]*bw[c];
        }
#pragma unroll
        for (int r = 0; r < 8; r++)
#pragma unroll
            for (int c = 0; c < 4; c++) accd[r][c] += (double)blk[r][c];
        __syncthreads();
    }
    double* red = (double*)&ws[0][0];
#pragma unroll
    for (int r = 0; r < 8; r++) {
        double p = 0.0;
#pragma unroll
        for (int c = 0; c < 4; c++) {
            float h = (float)accd[r][c];           // reference's fp32 h
            p += (double)fmaxf(h, 0.f) * (double)w2s[tx + 64*c];
        }
        red[(ty*8 + r)*65 + tx] = p;
    }
    __syncthreads();
    if (tid < 32) {
        double s = 0.0;
#pragma unroll 8
        for (int x = 0; x < 64; x++) s += red[tid*65 + x];
        g_scores[r0 + tid] = (float)(1.0 / (1.0 + exp(-s)));
    }
}

// =============================================================================
// Kernel 2: per-batch bitonic sort, descending score, ascending idx tiebreak.
// =============================================================================
__global__ __launch_bounds__(1024) void sort_kernel()
{
    __shared__ float key[NT];
    __shared__ int   sidx[NT];
    int b = blockIdx.x, tid = threadIdx.x;
    for (int i = tid; i < NT; i += 1024) { key[i] = g_scores[b*NT + i]; sidx[i] = i; }
    __syncthreads();
    for (int k = 2; k <= NT; k <<= 1) {
        for (int j = k >> 1; j > 0; j >>= 1) {
#pragma unroll
            for (int l = 0; l < 2; l++) {
                int i = tid + l*1024;
                int ixj = i ^ j;
                if (ixj > i) {
                    bool up = ((i & k) == 0);
                    float ka = key[i], kb = key[ixj];
                    int ia = sidx[i], ib = sidx[ixj];
                    bool gt = (ka < kb) || (ka == kb && ia > ib);
                    if (gt == up) {
                        key[i] = kb; key[ixj] = ka;
                        sidx[i] = ib; sidx[ixj] = ia;
                    }
                }
            }
            __syncthreads();
        }
    }
    for (int i = tid; i < NT; i += 1024) g_sscore[b*NT + i] = key[i];
    if (tid < NP) g_summap[b*NP + tid] = b*NT + sidx[tid];
}

// =============================================================================
// Kernel 3: fp32 GEMM, 64x256 block tile, 8x8 micro-tile (LDS/FMA balanced).
// C[M,N] = A[rowmap(m), K] @ B[K, N]
// =============================================================================
__global__ __launch_bounds__(256) void gemm64(
    const float* __restrict__ A, const float* __restrict__ Bm, float* __restrict__ C,
    int K, int N, const int* __restrict__ rowmap)
{
    __shared__ float xs[64][33];
    __shared__ float ws[32][257];
    int tid = threadIdx.x;
    int tx = tid & 31, ty = tid >> 5;          // 32 cols-threads x 8 row-groups
    int r0 = blockIdx.x * 64, c0 = blockIdx.y * 256;
    int arl[8];
#pragma unroll
    for (int l = 0; l < 8; l++) {
        int t = (tid + l*256) >> 5;
        arl[l] = rowmap ? rowmap[r0 + t] : (r0 + t);
    }
    float acc[8][8];
#pragma unroll
    for (int r = 0; r < 8; r++)
#pragma unroll
        for (int c = 0; c < 8; c++) acc[r][c] = 0.f;

    for (int k0 = 0; k0 < K; k0 += 32) {
#pragma unroll
        for (int l = 0; l < 8; l++) {
            int idx = tid + l*256; int t = idx >> 5, kk = idx & 31;
            xs[t][kk] = A[(size_t)arl[l]*K + k0 + kk];
        }
#pragma unroll
        for (int l = 0; l < 32; l++) {
            int idx = tid + l*256; int kk = idx >> 8, j = idx & 255;
            ws[kk][j] = Bm[(size_t)(k0 + kk)*N + c0 + j];
        }
        __syncthreads();
#pragma unroll 4
        for (int kk = 0; kk < 32; kk++) {
            float bw[8], ax[8];
#pragma unroll
            for (int c = 0; c < 8; c++) bw[c] = ws[kk][tx + 32*c];
#pragma unroll
            for (int r = 0; r < 8; r++) ax[r] = xs[ty*8 + r][kk];
#pragma unroll
            for (int r = 0; r < 8; r++)
#pragma unroll
                for (int c = 0; c < 8; c++) acc[r][c] += ax[r]*bw[c];
        }
        __syncthreads();
    }
#pragma unroll
    for (int r = 0; r < 8; r++)
#pragma unroll
        for (int c = 0; c < 8; c++)
            C[(size_t)(r0 + ty*8 + r)*N + c0 + tx + 32*c] = acc[r][c];
}

// =============================================================================
// Kernel 4: serial priority-pool scan — ONE WARP per batch, no block barriers.
// Lane-cached (min,argmin) over 16 owned slots + warp bfly argmin; early exit
// since sorted scores are descending (min only grows, imp only shrinks).
// =============================================================================
__device__ __forceinline__ void warpArgMinB(float &v, int &ix) {
#pragma unroll
    for (int off = 16; off; off >>= 1) {
        float ov = __shfl_xor_sync(0xffffffffu, v, off);
        int   oi = __shfl_xor_sync(0xffffffffu, ix, off);
        if (ov < v || (ov == v && oi < ix)) { v = ov; ix = oi; }
    }
}

__global__ __launch_bounds__(32) void update_kernel(
    const float* __restrict__ pri_in, const int* __restrict__ counts_in,
    float* __restrict__ out_pri, float* __restrict__ out_cnt)
{
    int b = blockIdx.x, lane = threadIdx.x;
    __shared__ float pri[NP];
    __shared__ float ssc[NP];
    __shared__ int   srcS[NP];
#pragma unroll
    for (int j = 0; j < 16; j++) {
        int s = j*32 + lane;
        pri[s]  = pri_in[b*NP + s];
        ssc[s]  = g_sscore[b*NT + s];
        srcS[s] = -1;
    }
    __syncwarp();
    int cnt = counts_in[b];

    float lmin = pri[lane]; int lidx = lane;
#pragma unroll
    for (int j = 1; j < 16; j++) {
        int s = j*32 + lane; float p = pri[s];
        if (p < lmin) { lmin = p; lidx = s; }
    }
    float gmin = lmin; int gidx = lidx;
    warpArgMinB(gmin, gidx);

    for (int i = 0; i < NP; i++) {
        float imp = ssc[i];
        if (!(imp > 0.5f)) break;                     // all later items also fail
        if (cnt < NP) {                               // ---- insert phase ----
            int s = cnt;
            bool dirtyG = (s == gidx);
            if (lane == (s & 31)) {
                pri[s] = imp; srcS[s] = i;
                if (s == lidx) {                      // recompute lane min
                    lmin = pri[lane]; lidx = lane;
#pragma unroll
                    for (int j = 1; j < 16; j++) {
                        int t = j*32 + lane; float p = pri[t];
                        if (p < lmin) { lmin = p; lidx = t; }
                    }
                } else if (imp < lmin || (imp == lmin && s < lidx)) {
                    lmin = imp; lidx = s;
                }
            }
            __syncwarp();
            if (dirtyG) { gmin = lmin; gidx = lidx; warpArgMinB(gmin, gidx); }
            else if (imp < gmin || (imp == gmin && s < gidx)) { gmin = imp; gidx = s; }
            cnt++;
        }
        if (cnt >= NP) {                              // ---- replace-min phase ----
            if (!(imp > gmin)) break;                 // no later item can act
            int s = gidx;
            if (lane == (s & 31)) {
                pri[s] = imp; srcS[s] = i;            // s == this lane's lidx
                lmin = pri[lane]; lidx = lane;
#pragma unroll
                for (int j = 1; j < 16; j++) {
                    int t = j*32 + lane; float p = pri[t];
                    if (p < lmin) { lmin = p; lidx = t; }
                }
            }
            __syncwarp();
            gmin = lmin; gidx = lidx; warpArgMinB(gmin, gidx);
        }
    }
#pragma unroll
    for (int j = 0; j < 16; j++) {
        int s = j*32 + lane;
        if (out_pri) out_pri[b*NP + s] = pri[s];
        g_src[b*NP + s] = srcS[s];
    }
    if (lane == 0) {
        g_counts[b] = cnt;
        if (out_cnt) out_cnt[b] = (float)cnt;
    }
}

// =============================================================================
// Kernel 5: materialize final pool rows
// =============================================================================
__global__ __launch_bounds__(256) void pool_finalize(
    const float* __restrict__ pool_in, float* __restrict__ out_pool)
{
    int row = blockIdx.x;                 // 0..4095
    int b = row >> 9;
    int s = g_src[row];
    const float* srcrow = (s >= 0) ? (g_summ + (size_t)(b*NP + s)*NS)
                                   : (pool_in + (size_t)row*NS);
    float v = srcrow[threadIdx.x];
    g_poolf[(size_t)row*NS + threadIdx.x] = v;
    if (out_pool) out_pool[(size_t)row*NS + threadIdx.x] = v;
}

// =============================================================================
// Kernel 6: fused attention, 8x8 micro-tiles, 4x64 thread grid over 32x512.
// =============================================================================
#define WPITCH 521
#define LPITCH 513
__global__ __launch_bounds__(256) void attn_kernel(float* __restrict__ out_retr)
{
    extern __shared__ float sm[];
    float (*xs)[33]    = (float (*)[33])sm;                       // 32 x 33
    float* ws          = sm + 32*33;                              // [32][521]
    float (*L)[LPITCH] = (float (*)[LPITCH])(sm + 32*33 + 32*WPITCH); // 32 x 513

    int tid = threadIdx.x;
    int tx = tid & 63, ty = tid >> 6;     // 64 col-threads x 4 row-groups
    int warp = tid >> 5, lane = tid & 31;
    int b  = blockIdx.x >> 6;
    int t0 = (blockIdx.x & 63) * 32;
    const float* qb = g_q + ((size_t)b*NT + t0)*NS;
    const float* kb = g_k + (size_t)b*NP*NS;
    const float* vb = g_v + (size_t)b*NP*ND;

    // ---- Phase A: L[32][512] = qb @ kb^T * (1/16) ----
    {
        float acc[8][8];
#pragma unroll
        for (int r = 0; r < 8; r++)
#pragma unroll
            for (int c = 0; c < 8; c++) acc[r][c] = 0.f;
        for (int k0 = 0; k0 < NS; k0 += 32) {
#pragma unroll
            for (int l = 0; l < 4; l++) {
                int idx = tid + l*256; int t = idx >> 5, kk = idx & 31;
                xs[t][kk] = qb[(size_t)t*NS + k0 + kk];
            }
#pragma unroll
            for (int rr = 0; rr < 64; rr++) {     // transposed K load
                int p = warp*64 + rr;
                ws[lane*WPITCH + p] = kb[(size_t)p*NS + k0 + lane];
            }
            __syncthreads();
#pragma unroll 4
            for (int kk = 0; kk < 32; kk++) {
                float bw[8], ax[8];
#pragma unroll
                for (int c = 0; c < 8; c++) bw[c] = ws[kk*WPITCH + tx + 64*c];
#pragma unroll
                for (int r = 0; r < 8; r++) ax[r] = xs[ty*8 + r][kk];
#pragma unroll
                for (int r = 0; r < 8; r++)
#pragma unroll
                    for (int c = 0; c < 8; c++) acc[r][c] += ax[r]*bw[c];
            }
            __syncthreads();
        }
#pragma unroll
        for (int r = 0; r < 8; r++)
#pragma unroll
            for (int c = 0; c < 8; c++)
                L[ty*8 + r][tx + 64*c] = acc[r][c] * 0.0625f;
    }
    __syncthreads();

    // ---- Phase B: masked softmax per row (8 threads/row) ----
    {
        int row = tid >> 3, sub = tid & 7;
        int cnt = g_counts[b];
        float m = -FLT_MAX;
        for (int p = sub; p < cnt; p += 8) m = fmaxf(m, L[row][p]);
#pragma unroll
        for (int off = 4; off; off >>= 1) m = fmaxf(m, __shfl_xor_sync(0xffffffffu, m, off));
        float s = 0.f;
        for (int p = sub; p < cnt; p += 8) {
            float e = expf(L[row][p] - m);
            L[row][p] = e; s += e;
        }
#pragma unroll
        for (int off = 4; off; off >>= 1) s += __shfl_xor_sync(0xffffffffu, s, off);
        float inv = (s > 0.f) ? 1.f/s : 0.f;
        for (int p = sub; p < NP; p += 8) L[row][p] = (p < cnt) ? L[row][p]*inv : 0.f;
    }
    __syncthreads();

    // ---- Phase C: out[32][1024] = L @ vb, two 512-col halves ----
    for (int cp = 0; cp < 2; cp++) {
        float acc[8][8];
#pragma unroll
        for (int r = 0; r < 8; r++)
#pragma unroll
            for (int c = 0; c < 8; c++) acc[r][c] = 0.f;
        for (int k0 = 0; k0 < NP; k0 += 32) {
#pragma unroll
            for (int l = 0; l < 64; l++) {
                int idx = tid + l*256; int kk = idx >> 9, j = idx & 511;
                ws[kk*WPITCH + j] = vb[(size_t)(k0 + kk)*ND + cp*512 + j];
            }
            __syncthreads();
#pragma unroll 4
            for (int kk = 0; kk < 32; kk++) {
                float bw[8], ax[8];
#pragma unroll
                for (int c = 0; c < 8; c++) bw[c] = ws[kk*WPITCH + tx + 64*c];
#pragma unroll
                for (int r = 0; r < 8; r++) ax[r] = L[ty*8 + r][k0 + kk];
#pragma unroll
                for (int r = 0; r < 8; r++)
#pragma unroll
                    for (int c = 0; c < 8; c++) acc[r][c] += ax[r]*bw[c];
            }
            __syncthreads();
        }
#pragma unroll
        for (int r = 0; r < 8; r++)
#pragma unroll
            for (int c = 0; c < 8; c++)
                out_retr[((size_t)b*NT + t0 + ty*8 + r)*ND + cp*512 + tx + 64*c] = acc[r][c];
    }
}

// =============================================================================
// launch
// =============================================================================
extern "C" void kernel_launch(void* const* d_in, const int* in_sizes, int n_in,
                              void* d_out, int out_size)
{
    const float* tokens = (const float*)d_in[0];
    const float* pool   = (const float*)d_in[1];
    const float* pri    = (const float*)d_in[2];
    const int*   counts = (const int*)  d_in[3];
    const float* w1     = (const float*)d_in[4];
    const float* w2     = (const float*)d_in[5];
    const float* w_sum  = (const float*)d_in[6];
    const float* wq     = (const float*)d_in[7];
    const float* wk     = (const float*)d_in[8];
    const float* wv     = (const float*)d_in[9];

    float* out = (float*)d_out;
    const int RETR = NB*NT*ND;
    const int POOL = NB*NP*NS;
    const int PRI  = NB*NP;
    float* out_retr = out;
    bool full = (out_size >= RETR + POOL + PRI + NB);
    float* out_pool = full ? out + RETR : nullptr;
    float* out_pri  = full ? out + RETR + POOL : nullptr;
    float* out_cnt  = full ? out + RETR + POOL + PRI : nullptr;

    float *p_summ, *p_poolf, *p_q, *p_k, *p_v;
    int *p_summap;
    cudaGetSymbolAddress((void**)&p_summ,   g_summ);
    cudaGetSymbolAddress((void**)&p_poolf,  g_poolf);
    cudaGetSymbolAddress((void**)&p_q,      g_q);
    cudaGetSymbolAddress((void**)&p_k,      g_k);
    cudaGetSymbolAddress((void**)&p_v,      g_v);
    cudaGetSymbolAddress((void**)&p_summap, g_summap);

    const int ATTN_SMEM = (32*33 + 32*WPITCH + 32*LPITCH) * 4;
    cudaFuncSetAttribute(attn_kernel, cudaFuncAttributeMaxDynamicSharedMemorySize, ATTN_SMEM);

    // 1. scores (high precision)
    score_kernel<<<(NB*NT)/32, 256>>>(tokens, w1, w2);
    // 2. sort + summary row map
    sort_kernel<<<NB, 1024>>>();
    // 3. summaries = gather(tokens) @ w_sum   [4096,1024]@[1024,256]
    gemm64<<<dim3((NB*NP)/64, 1), 256>>>(tokens, w_sum, p_summ, ND, NS, p_summap);
    // 4. serial pool update (one warp per batch)
    update_kernel<<<NB, 32>>>(pri, counts, out_pri, out_cnt);
    // 5. materialize final pool
    pool_finalize<<<NB*NP, NS>>>(pool, out_pool);
    // 6. q = tokens @ wq   [16384,1024]@[1024,256]
    gemm64<<<dim3((NB*NT)/64, 1), 256>>>(tokens, wq, p_q, ND, NS, nullptr);
    // 7. k = pool_final @ wk   [4096,256]@[256,256]
    gemm64<<<dim3((NB*NP)/64, 1), 256>>>(p_poolf, wk, p_k, NS, NS, nullptr);
    // 8. v = pool_final @ wv   [4096,256]@[256,1024]
    gemm64<<<dim3((NB*NP)/64, 4), 256>>>(p_poolf, wv, p_v, NS, ND, nullptr);
    // 9. fused attention -> retrieved
    attn_kernel<<<NB*(NT/32), 256, ATTN_SMEM>>>(out_retr);
}